// round 15
// baseline (speedup 1.0000x reference)
#include <cuda_runtime.h>
#include <cuda_bf16.h>
#include <cstdint>

#define VOCAB 96
#define TT 16
#define EE 64
#define LL 4
#define BB 16384
#define G 4
#define ROWS 64
#define NT 128

#define RS 144            // bf16 row stride bytes for KH
#define VTS 40            // VT row stride bytes (16 bf16 + pad)

// smem offsets (bytes) — all warp-private
#define O_KH   0
#define O_VT   9216
#define SMEM_BYTES (O_VT + 4 * 64 * VTS)   // 19456

#define TOTAL_UNITS (24 * 1024 + 1536)

__device__ __align__(16) uint4 g_wpk[TOTAL_UNITS];   // hi+lo units (final projection uses tail)
__device__ __align__(16) uint2 g_wph[24 * 1024];     // hi-only, layout [l][slot][nt][r][j][ks]

// ---------------- helpers ----------------
__device__ __forceinline__ uint32_t phi(float a, float b) {
    __nv_bfloat162 t = __floats2bfloat162_rn(a, b);
    return *reinterpret_cast<uint32_t*>(&t);
}
__device__ __forceinline__ uint32_t plo(float a, float b, uint32_t h) {
    float2 f = __bfloat1622float2(*reinterpret_cast<__nv_bfloat162*>(&h));
    __nv_bfloat162 t = __floats2bfloat162_rn(a - f.x, b - f.y);
    return *reinterpret_cast<uint32_t*>(&t);
}
__device__ __forceinline__ void mma16816(float d[4], uint32_t a0, uint32_t a1,
                                         uint32_t a2, uint32_t a3,
                                         uint32_t b0, uint32_t b1) {
    asm volatile(
        "mma.sync.aligned.m16n8k16.row.col.f32.bf16.bf16.f32 "
        "{%0,%1,%2,%3}, {%4,%5,%6,%7}, {%8,%9}, {%0,%1,%2,%3};"
        : "+f"(d[0]), "+f"(d[1]), "+f"(d[2]), "+f"(d[3])
        : "r"(a0), "r"(a1), "r"(a2), "r"(a3), "r"(b0), "r"(b1));
}
__device__ __forceinline__ void pack_hi_frags(const float act[8][4], uint32_t ah[16]) {
#pragma unroll
    for (int ks = 0; ks < 4; ks++) {
        const float* a0 = act[2 * ks];
        const float* a1 = act[2 * ks + 1];
        ah[4*ks+0] = phi(a0[0], a0[1]);
        ah[4*ks+1] = phi(a0[2], a0[3]);
        ah[4*ks+2] = phi(a1[0], a1[1]);
        ah[4*ks+3] = phi(a1[2], a1[3]);
    }
}
__device__ __forceinline__ void pack_frags(const float act[8][4],
                                           uint32_t ah[16], uint32_t al[16]) {
#pragma unroll
    for (int ks = 0; ks < 4; ks++) {
        const float* a0 = act[2 * ks];
        const float* a1 = act[2 * ks + 1];
        ah[4*ks+0] = phi(a0[0], a0[1]); al[4*ks+0] = plo(a0[0], a0[1], ah[4*ks+0]);
        ah[4*ks+1] = phi(a0[2], a0[3]); al[4*ks+1] = plo(a0[2], a0[3], ah[4*ks+1]);
        ah[4*ks+2] = phi(a1[0], a1[1]); al[4*ks+2] = plo(a1[0], a1[1], ah[4*ks+2]);
        ah[4*ks+3] = phi(a1[2], a1[3]); al[4*ks+3] = plo(a1[2], a1[3], ah[4*ks+3]);
    }
}
// 1-term GEMM, repacked weights: per nt, two LDG.128 cover all 4 k-steps
template <int NTL>
__device__ __forceinline__ void gemm1(const uint32_t ah[16],
                                      const uint4* __restrict__ wu,
                                      float acc[NTL][4], int r, int j) {
    const uint4* base = wu + (r * 4 + j) * 2;
#pragma unroll
    for (int nt = 0; nt < NTL; nt++) {
        uint4 bA = __ldg(base + nt * 64);
        uint4 bB = __ldg(base + nt * 64 + 1);
        mma16816(acc[nt], ah[0],  ah[1],  ah[2],  ah[3],  bA.x, bA.y);
        mma16816(acc[nt], ah[4],  ah[5],  ah[6],  ah[7],  bA.z, bA.w);
        mma16816(acc[nt], ah[8],  ah[9],  ah[10], ah[11], bB.x, bB.y);
        mma16816(acc[nt], ah[12], ah[13], ah[14], ah[15], bB.z, bB.w);
    }
}
// 3-term GEMM (final projection, old unit layout)
template <int NTL>
__device__ __forceinline__ void gemm3(const uint32_t ah[16], const uint32_t al[16],
                                      const uint4* __restrict__ wu,
                                      float acc[NTL][4], int r, int j) {
#pragma unroll
    for (int ks = 0; ks < 4; ks++) {
        const uint32_t* AH = ah + 4 * ks;
        const uint32_t* AL = al + 4 * ks;
#pragma unroll
        for (int nt = 0; nt < NTL; nt++) {
            uint4 b = __ldg(wu + ((nt * 4 + ks) * 8 + r) * 4 + j);
            mma16816(acc[nt], AH[0], AH[1], AH[2], AH[3], b.x, b.y);
            mma16816(acc[nt], AL[0], AL[1], AL[2], AL[3], b.x, b.y);
            mma16816(acc[nt], AH[0], AH[1], AH[2], AH[3], b.z, b.w);
        }
    }
}
__device__ __forceinline__ void fstore_hi(char* B, int m0, int r, int j,
                                          const float a[8][4]) {
#pragma unroll
    for (int nt = 0; nt < 8; nt++) {
        uint32_t co = (uint32_t)(nt * 16 + j * 4);
        *reinterpret_cast<uint32_t*>(B + (m0 + r) * RS + co) = phi(a[nt][0], a[nt][1]);
        *reinterpret_cast<uint32_t*>(B + (m0 + r + 8) * RS + co) = phi(a[nt][2], a[nt][3]);
    }
}
__device__ __forceinline__ void fstore_vt(char* vt, int r, int j, const float a[8][4]) {
#pragma unroll
    for (int nt = 0; nt < 8; nt++) {
        int c = nt * 8 + 2 * j;
        *reinterpret_cast<__nv_bfloat16*>(vt + c * VTS + r * 2) = __float2bfloat16(a[nt][0]);
        *reinterpret_cast<__nv_bfloat16*>(vt + (c + 1) * VTS + r * 2) = __float2bfloat16(a[nt][1]);
        *reinterpret_cast<__nv_bfloat16*>(vt + c * VTS + (r + 8) * 2) = __float2bfloat16(a[nt][2]);
        *reinterpret_cast<__nv_bfloat16*>(vt + (c + 1) * VTS + (r + 8) * 2) = __float2bfloat16(a[nt][3]);
    }
}
__device__ __forceinline__ void ln_frag(float x[8][4], const float* __restrict__ g,
                                        const float* __restrict__ b, int j) {
    float s0 = 0.f, q0 = 0.f, s1 = 0.f, q1 = 0.f;
#pragma unroll
    for (int nt = 0; nt < 8; nt++) {
        s0 += x[nt][0] + x[nt][1]; q0 += x[nt][0] * x[nt][0] + x[nt][1] * x[nt][1];
        s1 += x[nt][2] + x[nt][3]; q1 += x[nt][2] * x[nt][2] + x[nt][3] * x[nt][3];
    }
    s0 += __shfl_xor_sync(0xffffffffu, s0, 1); q0 += __shfl_xor_sync(0xffffffffu, q0, 1);
    s1 += __shfl_xor_sync(0xffffffffu, s1, 1); q1 += __shfl_xor_sync(0xffffffffu, q1, 1);
    s0 += __shfl_xor_sync(0xffffffffu, s0, 2); q0 += __shfl_xor_sync(0xffffffffu, q0, 2);
    s1 += __shfl_xor_sync(0xffffffffu, s1, 2); q1 += __shfl_xor_sync(0xffffffffu, q1, 2);
    float m0 = s0 * (1.f / 64.f), m1 = s1 * (1.f / 64.f);
    float r0 = rsqrtf(q0 * (1.f / 64.f) - m0 * m0 + 1e-5f);
    float r1 = rsqrtf(q1 * (1.f / 64.f) - m1 * m1 + 1e-5f);
#pragma unroll
    for (int nt = 0; nt < 8; nt++) {
        int c = nt * 8 + j * 2;
        float2 gg = __ldg(reinterpret_cast<const float2*>(g + c));
        float2 bb = __ldg(reinterpret_cast<const float2*>(b + c));
        x[nt][0] = (x[nt][0] - m0) * r0 * gg.x + bb.x;
        x[nt][1] = (x[nt][1] - m0) * r0 * gg.y + bb.y;
        x[nt][2] = (x[nt][2] - m1) * r1 * gg.x + bb.x;
        x[nt][3] = (x[nt][3] - m1) * r1 * gg.y + bb.y;
    }
}

// ---------------- prep kernel ----------------
__global__ void prep_kernel(const float* __restrict__ Wq, const float* __restrict__ Wk,
                            const float* __restrict__ Wv, const float* __restrict__ Wo,
                            const float* __restrict__ W1, const float* __restrict__ W2,
                            const float* __restrict__ Wout) {
    int gid = blockIdx.x * 256 + threadIdx.x;
    if (gid >= TOTAL_UNITS) return;
    if (gid < 24 * 1024) {
        // g_wph, NEW layout: u = ((nt*8 + r)*4 + j)*4 + ks
        int sidx = gid >> 10;
        int u = gid & 1023;
        int l = sidx / 6, slot = sidx % 6;
        int ks = u & 3, j = (u >> 2) & 3, r = (u >> 4) & 7, nt = u >> 7;
        int c = nt * 8 + r;
        int k0 = ks * 16 + j * 2;
        float v00, v80;
        if (slot < 3) {
            const float* W = (slot == 0) ? Wq : (slot == 1) ? Wk : Wv;
            const float* p = W + l * 4096 + (c >> 4) * 1024 + (c & 15);
            float v01 = p[(k0 + 1) * 16], v81 = p[(k0 + 9) * 16];
            v00 = p[k0 * 16]; v80 = p[(k0 + 8) * 16];
            g_wph[gid] = make_uint2(phi(v00, v01), phi(v80, v81));
        } else {
            const float* W = (slot == 3) ? Wo : (slot == 4) ? W1 : W2;
            const float* p = W + l * 4096 + c;
            float v01 = p[(k0 + 1) * 64], v81 = p[(k0 + 9) * 64];
            v00 = p[k0 * 64]; v80 = p[(k0 + 8) * 64];
            g_wph[gid] = make_uint2(phi(v00, v01), phi(v80, v81));
        }
    } else {
        // g_wpk final projection units, OLD layout
        int u = gid - 24 * 1024;
        int nt = u >> 7, ks = (u >> 5) & 3, r = (u >> 2) & 7, j = u & 3;
        int c = nt * 8 + r;
        int k0 = ks * 16 + j * 2;
        const float* p = Wout + c;
        float v00 = p[k0 * 96], v01 = p[(k0 + 1) * 96];
        float v80 = p[(k0 + 8) * 96], v81 = p[(k0 + 9) * 96];
        uint32_t h0 = phi(v00, v01), h8 = phi(v80, v81);
        uint32_t l0 = plo(v00, v01, h0), l8 = plo(v80, v81, h8);
        g_wpk[gid] = make_uint4(h0, h8, l0, l8);
    }
}

// ---------------- main kernel ----------------
__global__ void __launch_bounds__(NT, 4)
bert_mma_kernel(const int* __restrict__ data, const float* __restrict__ tok_emb,
                const float* __restrict__ pos_emb,
                const float* __restrict__ bo,
                const float* __restrict__ ln1g, const float* __restrict__ ln1b,
                const float* __restrict__ ln2g, const float* __restrict__ ln2b,
                const float* __restrict__ b1, const float* __restrict__ b2,
                const float* __restrict__ bout, float* __restrict__ out) {
    extern __shared__ char sm[];
    char* KH = sm + O_KH;

    const int tid = threadIdx.x;
    const int w = tid >> 5, lane = tid & 31;
    const int r = lane >> 2, j = lane & 3;
    const int m0 = w * 16;
    const int blk = blockIdx.x;
    char* vt = sm + O_VT + w * 64 * VTS;
    const uint4* wph4 = reinterpret_cast<const uint4*>(&g_wph[0]);

    // -------- embedding (fragment layout)
    float x[8][4];
    {
        int b = blk * G + w;
        int tokA = data[b * TT + r], tokB = data[b * TT + r + 8];
#pragma unroll
        for (int nt = 0; nt < 8; nt++) {
            int c = nt * 8 + j * 2;
            float2 tA = __ldg(reinterpret_cast<const float2*>(tok_emb + tokA * EE + c));
            float2 tB = __ldg(reinterpret_cast<const float2*>(tok_emb + tokB * EE + c));
            float2 pA = __ldg(reinterpret_cast<const float2*>(pos_emb + r * EE + c));
            float2 pB = __ldg(reinterpret_cast<const float2*>(pos_emb + (r + 8) * EE + c));
            x[nt][0] = tA.x + pA.x; x[nt][1] = tA.y + pA.y;
            x[nt][2] = tB.x + pB.x; x[nt][3] = tB.y + pB.y;
        }
    }

    for (int l = 0; l < LL; l++) {
        const uint4* wl = wph4 + l * 3072;   // 6 slots x 512 uint4

        uint32_t pah[16];
        pack_hi_frags(x, pah);

        // Q -> registers (A-frags per head, pre-scaled)
        uint32_t qa[16];
        {
            float acc[8][4];
#pragma unroll
            for (int nt = 0; nt < 8; nt++) { acc[nt][0] = acc[nt][1] = acc[nt][2] = acc[nt][3] = 0.f; }
            gemm1<8>(pah, wl + 0, acc, r, j);
#pragma unroll
            for (int h = 0; h < 4; h++) {
                qa[4*h+0] = phi(acc[2*h][0] * 0.25f, acc[2*h][1] * 0.25f);
                qa[4*h+1] = phi(acc[2*h][2] * 0.25f, acc[2*h][3] * 0.25f);
                qa[4*h+2] = phi(acc[2*h+1][0] * 0.25f, acc[2*h+1][1] * 0.25f);
                qa[4*h+3] = phi(acc[2*h+1][2] * 0.25f, acc[2*h+1][3] * 0.25f);
            }
        }
        // K -> smem rows (bf16 hi)
        {
            float acc[8][4];
#pragma unroll
            for (int nt = 0; nt < 8; nt++) { acc[nt][0] = acc[nt][1] = acc[nt][2] = acc[nt][3] = 0.f; }
            gemm1<8>(pah, wl + 512, acc, r, j);
            fstore_hi(KH, m0, r, j, acc);
        }
        // V -> smem transposed (bf16 hi)
        {
            float acc[8][4];
#pragma unroll
            for (int nt = 0; nt < 8; nt++) { acc[nt][0] = acc[nt][1] = acc[nt][2] = acc[nt][3] = 0.f; }
            gemm1<8>(pah, wl + 1024, acc, r, j);
            fstore_vt(vt, r, j, acc);
        }
        __syncwarp();

        // -------- attention: fragment-native, no max-subtraction (scores are tiny)
        uint32_t oa[16];
#pragma unroll
        for (int h = 0; h < 4; h++) {
            const uint32_t* q4 = qa + 4 * h;
            float s0[4] = {0.f, 0.f, 0.f, 0.f}, s1[4] = {0.f, 0.f, 0.f, 0.f};
            {
                const char* k0p = KH + (m0 + r) * RS + h * 32;
                uint32_t b0 = *reinterpret_cast<const uint32_t*>(k0p + 4 * j);
                uint32_t b1 = *reinterpret_cast<const uint32_t*>(k0p + 16 + 4 * j);
                mma16816(s0, q4[0], q4[1], q4[2], q4[3], b0, b1);
                const char* k1p = KH + (m0 + 8 + r) * RS + h * 32;
                b0 = *reinterpret_cast<const uint32_t*>(k1p + 4 * j);
                b1 = *reinterpret_cast<const uint32_t*>(k1p + 16 + 4 * j);
                mma16816(s1, q4[0], q4[1], q4[2], q4[3], b0, b1);
            }
            float e00 = __expf(s0[0]), e01 = __expf(s0[1]);
            float e10 = __expf(s1[0]), e11 = __expf(s1[1]);
            float f00 = __expf(s0[2]), f01 = __expf(s0[3]);
            float f10 = __expf(s1[2]), f11 = __expf(s1[3]);
            float sum0 = e00 + e01 + e10 + e11;
            float sum1 = f00 + f01 + f10 + f11;
            sum0 += __shfl_xor_sync(0xffffffffu, sum0, 1);
            sum0 += __shfl_xor_sync(0xffffffffu, sum0, 2);
            sum1 += __shfl_xor_sync(0xffffffffu, sum1, 1);
            sum1 += __shfl_xor_sync(0xffffffffu, sum1, 2);
            float iv0 = 1.f / sum0, iv1 = 1.f / sum1;
            uint32_t p0 = phi(e00, e01);
            uint32_t p1 = phi(f00, f01);
            uint32_t p2 = phi(e10, e11);
            uint32_t p3 = phi(f10, f11);
            float o0[4] = {0.f, 0.f, 0.f, 0.f}, o1[4] = {0.f, 0.f, 0.f, 0.f};
            {
                const char* v0p = vt + (h * 16 + r) * VTS;
                uint32_t b0 = *reinterpret_cast<const uint32_t*>(v0p + 4 * j);
                uint32_t b1 = *reinterpret_cast<const uint32_t*>(v0p + 16 + 4 * j);
                mma16816(o0, p0, p1, p2, p3, b0, b1);
                const char* v1p = vt + (h * 16 + 8 + r) * VTS;
                b0 = *reinterpret_cast<const uint32_t*>(v1p + 4 * j);
                b1 = *reinterpret_cast<const uint32_t*>(v1p + 16 + 4 * j);
                mma16816(o1, p0, p1, p2, p3, b0, b1);
            }
            oa[4*h+0] = phi(o0[0] * iv0, o0[1] * iv0);
            oa[4*h+1] = phi(o0[2] * iv1, o0[3] * iv1);
            oa[4*h+2] = phi(o1[0] * iv0, o1[1] * iv0);
            oa[4*h+3] = phi(o1[2] * iv1, o1[3] * iv1);
        }

        // -------- o @ Wo + bo + x ; LN1
        {
            float acc[8][4];
#pragma unroll
            for (int nt = 0; nt < 8; nt++) { acc[nt][0] = acc[nt][1] = acc[nt][2] = acc[nt][3] = 0.f; }
            gemm1<8>(oa, wl + 1536, acc, r, j);
#pragma unroll
            for (int nt = 0; nt < 8; nt++) {
                int c = nt * 8 + j * 2;
                float2 bb = __ldg(reinterpret_cast<const float2*>(bo + l * 64 + c));
                x[nt][0] += acc[nt][0] + bb.x; x[nt][1] += acc[nt][1] + bb.y;
                x[nt][2] += acc[nt][2] + bb.x; x[nt][3] += acc[nt][3] + bb.y;
            }
            ln_frag(x, ln1g + l * 64, ln1b + l * 64, j);
        }

        // -------- FF1 -> relu -> FF2 -> residual -> LN2
        {
            uint32_t fah[16];
            pack_hi_frags(x, fah);
            float t1[8][4];
#pragma unroll
            for (int nt = 0; nt < 8; nt++) { t1[nt][0] = t1[nt][1] = t1[nt][2] = t1[nt][3] = 0.f; }
            gemm1<8>(fah, wl + 2048, t1, r, j);
#pragma unroll
            for (int nt = 0; nt < 8; nt++) {
                int c = nt * 8 + j * 2;
                float2 bb = __ldg(reinterpret_cast<const float2*>(b1 + l * 64 + c));
                t1[nt][0] = fmaxf(t1[nt][0] + bb.x, 0.f); t1[nt][1] = fmaxf(t1[nt][1] + bb.y, 0.f);
                t1[nt][2] = fmaxf(t1[nt][2] + bb.x, 0.f); t1[nt][3] = fmaxf(t1[nt][3] + bb.y, 0.f);
            }
            uint32_t gah[16];
            pack_hi_frags(t1, gah);
            float acc[8][4];
#pragma unroll
            for (int nt = 0; nt < 8; nt++) { acc[nt][0] = acc[nt][1] = acc[nt][2] = acc[nt][3] = 0.f; }
            gemm1<8>(gah, wl + 2560, acc, r, j);
#pragma unroll
            for (int nt = 0; nt < 8; nt++) {
                int c = nt * 8 + j * 2;
                float2 bb = __ldg(reinterpret_cast<const float2*>(b2 + l * 64 + c));
                x[nt][0] += acc[nt][0] + bb.x; x[nt][1] += acc[nt][1] + bb.y;
                x[nt][2] += acc[nt][2] + bb.x; x[nt][3] += acc[nt][3] + bb.y;
            }
            ln_frag(x, ln2g + l * 64, ln2b + l * 64, j);
        }
    }

    // -------- final projection: out = x @ Wout + bout (3-term)
    {
        uint32_t fah[16], fal[16];
        pack_frags(x, fah, fal);
        float acc[12][4];
#pragma unroll
        for (int nt = 0; nt < 12; nt++) { acc[nt][0] = acc[nt][1] = acc[nt][2] = acc[nt][3] = 0.f; }
        gemm3<12>(fah, fal, g_wpk + 24 * 1024, acc, r, j);
        float* o0 = out + (size_t)(blk * ROWS + m0 + r) * VOCAB;
        float* o1 = out + (size_t)(blk * ROWS + m0 + r + 8) * VOCAB;
#pragma unroll
        for (int nt = 0; nt < 12; nt++) {
            int c = nt * 8 + j * 2;
            float2 bb = __ldg(reinterpret_cast<const float2*>(bout + c));
            *reinterpret_cast<float2*>(o0 + c) = make_float2(acc[nt][0] + bb.x, acc[nt][1] + bb.y);
            *reinterpret_cast<float2*>(o1 + c) = make_float2(acc[nt][2] + bb.x, acc[nt][3] + bb.y);
        }
    }
}

extern "C" void kernel_launch(void* const* d_in, const int* in_sizes, int n_in,
                              void* d_out, int out_size) {
    const int*   data    = (const int*)d_in[0];
    const float* tok_emb = (const float*)d_in[1];
    const float* pos_emb = (const float*)d_in[2];
    const float* Wq      = (const float*)d_in[3];
    const float* Wk      = (const float*)d_in[4];
    const float* Wv      = (const float*)d_in[5];
    const float* Wo      = (const float*)d_in[6];
    const float* bo      = (const float*)d_in[7];
    const float* ln1g    = (const float*)d_in[8];
    const float* ln1b    = (const float*)d_in[9];
    const float* ln2g    = (const float*)d_in[10];
    const float* ln2b    = (const float*)d_in[11];
    const float* W1      = (const float*)d_in[12];
    const float* b1      = (const float*)d_in[13];
    const float* W2      = (const float*)d_in[14];
    const float* b2      = (const float*)d_in[15];
    const float* Wout    = (const float*)d_in[16];
    const float* bout    = (const float*)d_in[17];
    float* out = (float*)d_out;

    prep_kernel<<<(TOTAL_UNITS + 255) / 256, 256>>>(Wq, Wk, Wv, Wo, W1, W2, Wout);
    cudaFuncSetAttribute(bert_mma_kernel,
                         cudaFuncAttributeMaxDynamicSharedMemorySize, SMEM_BYTES);
    bert_mma_kernel<<<BB / G, NT, SMEM_BYTES>>>(
        data, tok_emb, pos_emb, bo, ln1g, ln1b, ln2g, ln2b,
        b1, b2, bout, out);
}

// round 16
// speedup vs baseline: 1.2027x; 1.2027x over previous
#include <cuda_runtime.h>
#include <cuda_bf16.h>
#include <cstdint>

#define VOCAB 96
#define TT 16
#define EE 64
#define LL 4
#define BB 16384
#define G 4
#define ROWS 64
#define NT 128

#define RS 144            // bf16 row stride bytes for KH
#define VTS 40            // VT row stride bytes

#define O_KH   0
#define O_VT   9216
#define SMEM_BYTES (O_VT + 4 * 64 * VTS)   // 19456

// g_wph4: 24 slots x 512 uint4 (two k-steps per unit), lane-contiguous
#define WPH4_UNITS (24 * 512)
#define WOUT_UNITS 1536
#define PREP_TOTAL (WPH4_UNITS + WOUT_UNITS)

__device__ __align__(16) uint4 g_wph4[WPH4_UNITS];
__device__ __align__(16) uint4 g_wout[WOUT_UNITS];

// ---------------- helpers ----------------
__device__ __forceinline__ uint32_t phi(float a, float b) {
    __nv_bfloat162 t = __floats2bfloat162_rn(a, b);
    return *reinterpret_cast<uint32_t*>(&t);
}
__device__ __forceinline__ uint32_t plo(float a, float b, uint32_t h) {
    float2 f = __bfloat1622float2(*reinterpret_cast<__nv_bfloat162*>(&h));
    __nv_bfloat162 t = __floats2bfloat162_rn(a - f.x, b - f.y);
    return *reinterpret_cast<uint32_t*>(&t);
}
__device__ __forceinline__ void mma16816(float d[4], uint32_t a0, uint32_t a1,
                                         uint32_t a2, uint32_t a3,
                                         uint32_t b0, uint32_t b1) {
    asm volatile(
        "mma.sync.aligned.m16n8k16.row.col.f32.bf16.bf16.f32 "
        "{%0,%1,%2,%3}, {%4,%5,%6,%7}, {%8,%9}, {%0,%1,%2,%3};"
        : "+f"(d[0]), "+f"(d[1]), "+f"(d[2]), "+f"(d[3])
        : "r"(a0), "r"(a1), "r"(a2), "r"(a3), "r"(b0), "r"(b1));
}
__device__ __forceinline__ void pack_hi_frags(const float act[8][4], uint32_t ah[16]) {
#pragma unroll
    for (int ks = 0; ks < 4; ks++) {
        const float* a0 = act[2 * ks];
        const float* a1 = act[2 * ks + 1];
        ah[4*ks+0] = phi(a0[0], a0[1]);
        ah[4*ks+1] = phi(a0[2], a0[3]);
        ah[4*ks+2] = phi(a1[0], a1[1]);
        ah[4*ks+3] = phi(a1[2], a1[3]);
    }
}
__device__ __forceinline__ void pack_frags(const float act[8][4],
                                           uint32_t ah[16], uint32_t al[16]) {
#pragma unroll
    for (int ks = 0; ks < 4; ks++) {
        const float* a0 = act[2 * ks];
        const float* a1 = act[2 * ks + 1];
        ah[4*ks+0] = phi(a0[0], a0[1]); al[4*ks+0] = plo(a0[0], a0[1], ah[4*ks+0]);
        ah[4*ks+1] = phi(a0[2], a0[3]); al[4*ks+1] = plo(a0[2], a0[3], ah[4*ks+1]);
        ah[4*ks+2] = phi(a1[0], a1[1]); al[4*ks+2] = plo(a1[0], a1[1], ah[4*ks+2]);
        ah[4*ks+3] = phi(a1[2], a1[3]); al[4*ks+3] = plo(a1[2], a1[3], ah[4*ks+3]);
    }
}
// 1-term GEMM, coalesced packed weights: unit ((nt*2+kk)*8+r)*4+j holds ks=2kk,2kk+1
template <int NTL>
__device__ __forceinline__ void gemm1(const uint32_t ah[16],
                                      const uint4* __restrict__ wu,
                                      float acc[NTL][4], int r, int j) {
    const uint4* base = wu + r * 4 + j;
#pragma unroll
    for (int nt = 0; nt < NTL; nt++) {
        uint4 bA = __ldg(base + nt * 64);
        uint4 bB = __ldg(base + nt * 64 + 32);
        mma16816(acc[nt], ah[0],  ah[1],  ah[2],  ah[3],  bA.x, bA.y);
        mma16816(acc[nt], ah[4],  ah[5],  ah[6],  ah[7],  bA.z, bA.w);
        mma16816(acc[nt], ah[8],  ah[9],  ah[10], ah[11], bB.x, bB.y);
        mma16816(acc[nt], ah[12], ah[13], ah[14], ah[15], bB.z, bB.w);
    }
}
// 3-term GEMM (final projection, R14 unit layout)
template <int NTL>
__device__ __forceinline__ void gemm3(const uint32_t ah[16], const uint32_t al[16],
                                      const uint4* __restrict__ wu,
                                      float acc[NTL][4], int r, int j) {
#pragma unroll
    for (int ks = 0; ks < 4; ks++) {
        const uint32_t* AH = ah + 4 * ks;
        const uint32_t* AL = al + 4 * ks;
#pragma unroll
        for (int nt = 0; nt < NTL; nt++) {
            uint4 b = __ldg(wu + ((nt * 4 + ks) * 8 + r) * 4 + j);
            mma16816(acc[nt], AH[0], AH[1], AH[2], AH[3], b.x, b.y);
            mma16816(acc[nt], AL[0], AL[1], AL[2], AL[3], b.x, b.y);
            mma16816(acc[nt], AH[0], AH[1], AH[2], AH[3], b.z, b.w);
        }
    }
}
__device__ __forceinline__ void fstore_hi(char* B, int m0, int r, int j,
                                          const float a[8][4]) {
#pragma unroll
    for (int nt = 0; nt < 8; nt++) {
        uint32_t co = (uint32_t)(nt * 16 + j * 4);
        *reinterpret_cast<uint32_t*>(B + (m0 + r) * RS + co) = phi(a[nt][0], a[nt][1]);
        *reinterpret_cast<uint32_t*>(B + (m0 + r + 8) * RS + co) = phi(a[nt][2], a[nt][3]);
    }
}
__device__ __forceinline__ void fstore_vt(char* vt, int r, int j, const float a[8][4]) {
#pragma unroll
    for (int nt = 0; nt < 8; nt++) {
        int c = nt * 8 + 2 * j;
        *reinterpret_cast<__nv_bfloat16*>(vt + c * VTS + r * 2) = __float2bfloat16(a[nt][0]);
        *reinterpret_cast<__nv_bfloat16*>(vt + (c + 1) * VTS + r * 2) = __float2bfloat16(a[nt][1]);
        *reinterpret_cast<__nv_bfloat16*>(vt + c * VTS + (r + 8) * 2) = __float2bfloat16(a[nt][2]);
        *reinterpret_cast<__nv_bfloat16*>(vt + (c + 1) * VTS + (r + 8) * 2) = __float2bfloat16(a[nt][3]);
    }
}
__device__ __forceinline__ void ln_frag(float x[8][4], const float* __restrict__ g,
                                        const float* __restrict__ b, int j) {
    float s0 = 0.f, q0 = 0.f, s1 = 0.f, q1 = 0.f;
#pragma unroll
    for (int nt = 0; nt < 8; nt++) {
        s0 += x[nt][0] + x[nt][1]; q0 += x[nt][0] * x[nt][0] + x[nt][1] * x[nt][1];
        s1 += x[nt][2] + x[nt][3]; q1 += x[nt][2] * x[nt][2] + x[nt][3] * x[nt][3];
    }
    s0 += __shfl_xor_sync(0xffffffffu, s0, 1); q0 += __shfl_xor_sync(0xffffffffu, q0, 1);
    s1 += __shfl_xor_sync(0xffffffffu, s1, 1); q1 += __shfl_xor_sync(0xffffffffu, q1, 1);
    s0 += __shfl_xor_sync(0xffffffffu, s0, 2); q0 += __shfl_xor_sync(0xffffffffu, q0, 2);
    s1 += __shfl_xor_sync(0xffffffffu, s1, 2); q1 += __shfl_xor_sync(0xffffffffu, q1, 2);
    float m0 = s0 * (1.f / 64.f), m1 = s1 * (1.f / 64.f);
    float r0 = rsqrtf(q0 * (1.f / 64.f) - m0 * m0 + 1e-5f);
    float r1 = rsqrtf(q1 * (1.f / 64.f) - m1 * m1 + 1e-5f);
#pragma unroll
    for (int nt = 0; nt < 8; nt++) {
        int c = nt * 8 + j * 2;
        float2 gg = __ldg(reinterpret_cast<const float2*>(g + c));
        float2 bb = __ldg(reinterpret_cast<const float2*>(b + c));
        x[nt][0] = (x[nt][0] - m0) * r0 * gg.x + bb.x;
        x[nt][1] = (x[nt][1] - m0) * r0 * gg.y + bb.y;
        x[nt][2] = (x[nt][2] - m1) * r1 * gg.x + bb.x;
        x[nt][3] = (x[nt][3] - m1) * r1 * gg.y + bb.y;
    }
}

// ---------------- prep kernel ----------------
__global__ void prep_kernel(const float* __restrict__ Wq, const float* __restrict__ Wk,
                            const float* __restrict__ Wv, const float* __restrict__ Wo,
                            const float* __restrict__ W1, const float* __restrict__ W2,
                            const float* __restrict__ Wout) {
    int gid = blockIdx.x * 256 + threadIdx.x;
    if (gid >= PREP_TOTAL) return;
    if (gid < WPH4_UNITS) {
        // layout: slot = gid/512 (l*6+s), u = gid%512 = ((nt*2+kk)*8+r)*4+j
        int sidx = gid >> 9;
        int u = gid & 511;
        int l = sidx / 6, slot = sidx % 6;
        int j = u & 3, r = (u >> 2) & 7, kk = (u >> 5) & 1, nt = u >> 6;
        int c = nt * 8 + r;
        uint32_t res[4];
#pragma unroll
        for (int t = 0; t < 2; t++) {
            int ks = 2 * kk + t;
            int k0 = ks * 16 + j * 2;
            float v00, v01, v80, v81;
            if (slot < 3) {
                const float* W = (slot == 0) ? Wq : (slot == 1) ? Wk : Wv;
                const float* p = W + l * 4096 + (c >> 4) * 1024 + (c & 15);
                v00 = p[k0 * 16]; v01 = p[(k0 + 1) * 16];
                v80 = p[(k0 + 8) * 16]; v81 = p[(k0 + 9) * 16];
            } else {
                const float* W = (slot == 3) ? Wo : (slot == 4) ? W1 : W2;
                const float* p = W + l * 4096 + c;
                v00 = p[k0 * 64]; v01 = p[(k0 + 1) * 64];
                v80 = p[(k0 + 8) * 64]; v81 = p[(k0 + 9) * 64];
            }
            res[2 * t] = phi(v00, v01);
            res[2 * t + 1] = phi(v80, v81);
        }
        g_wph4[gid] = make_uint4(res[0], res[1], res[2], res[3]);
    } else {
        int u = gid - WPH4_UNITS;
        int nt = u >> 7, ks = (u >> 5) & 3, r = (u >> 2) & 7, j = u & 3;
        int c = nt * 8 + r;
        int k0 = ks * 16 + j * 2;
        const float* p = Wout + c;
        float v00 = p[k0 * 96], v01 = p[(k0 + 1) * 96];
        float v80 = p[(k0 + 8) * 96], v81 = p[(k0 + 9) * 96];
        uint32_t h0 = phi(v00, v01), h8 = phi(v80, v81);
        uint32_t l0 = plo(v00, v01, h0), l8 = plo(v80, v81, h8);
        g_wout[u] = make_uint4(h0, h8, l0, l8);
    }
}

// ---------------- main kernel ----------------
__global__ void __launch_bounds__(NT, 4)
bert_mma_kernel(const int* __restrict__ data, const float* __restrict__ tok_emb,
                const float* __restrict__ pos_emb,
                const float* __restrict__ bo,
                const float* __restrict__ ln1g, const float* __restrict__ ln1b,
                const float* __restrict__ ln2g, const float* __restrict__ ln2b,
                const float* __restrict__ b1, const float* __restrict__ b2,
                const float* __restrict__ bout, float* __restrict__ out) {
    extern __shared__ char sm[];
    char* KH = sm + O_KH;

    const int tid = threadIdx.x;
    const int w = tid >> 5, lane = tid & 31;
    const int r = lane >> 2, j = lane & 3;
    const int m0 = w * 16;
    const int blk = blockIdx.x;
    char* vt = sm + O_VT + w * 64 * VTS;

    // -------- embedding (fragment layout)
    float x[8][4];
    {
        int b = blk * G + w;
        int tokA = data[b * TT + r], tokB = data[b * TT + r + 8];
#pragma unroll
        for (int nt = 0; nt < 8; nt++) {
            int c = nt * 8 + j * 2;
            float2 tA = __ldg(reinterpret_cast<const float2*>(tok_emb + tokA * EE + c));
            float2 tB = __ldg(reinterpret_cast<const float2*>(tok_emb + tokB * EE + c));
            float2 pA = __ldg(reinterpret_cast<const float2*>(pos_emb + r * EE + c));
            float2 pB = __ldg(reinterpret_cast<const float2*>(pos_emb + (r + 8) * EE + c));
            x[nt][0] = tA.x + pA.x; x[nt][1] = tA.y + pA.y;
            x[nt][2] = tB.x + pB.x; x[nt][3] = tB.y + pB.y;
        }
    }

    for (int l = 0; l < LL; l++) {
        const uint4* wl = g_wph4 + l * 3072;   // 6 slots x 512 uint4

        uint32_t pah[16];
        pack_hi_frags(x, pah);

        // Q -> registers (A-frags per head, pre-scaled)
        uint32_t qa[16];
        {
            float acc[8][4];
#pragma unroll
            for (int nt = 0; nt < 8; nt++) { acc[nt][0] = acc[nt][1] = acc[nt][2] = acc[nt][3] = 0.f; }
            gemm1<8>(pah, wl + 0, acc, r, j);
#pragma unroll
            for (int h = 0; h < 4; h++) {
                qa[4*h+0] = phi(acc[2*h][0] * 0.25f, acc[2*h][1] * 0.25f);
                qa[4*h+1] = phi(acc[2*h][2] * 0.25f, acc[2*h][3] * 0.25f);
                qa[4*h+2] = phi(acc[2*h+1][0] * 0.25f, acc[2*h+1][1] * 0.25f);
                qa[4*h+3] = phi(acc[2*h+1][2] * 0.25f, acc[2*h+1][3] * 0.25f);
            }
        }
        // K -> smem rows (bf16 hi)
        {
            float acc[8][4];
#pragma unroll
            for (int nt = 0; nt < 8; nt++) { acc[nt][0] = acc[nt][1] = acc[nt][2] = acc[nt][3] = 0.f; }
            gemm1<8>(pah, wl + 512, acc, r, j);
            fstore_hi(KH, m0, r, j, acc);
        }
        // V -> smem transposed (bf16 hi)
        {
            float acc[8][4];
#pragma unroll
            for (int nt = 0; nt < 8; nt++) { acc[nt][0] = acc[nt][1] = acc[nt][2] = acc[nt][3] = 0.f; }
            gemm1<8>(pah, wl + 1024, acc, r, j);
            fstore_vt(vt, r, j, acc);
        }
        __syncwarp();

        // -------- attention: fragment-native, no max-subtraction (scores tiny)
        uint32_t oa[16];
#pragma unroll
        for (int h = 0; h < 4; h++) {
            const uint32_t* q4 = qa + 4 * h;
            float s0[4] = {0.f, 0.f, 0.f, 0.f}, s1[4] = {0.f, 0.f, 0.f, 0.f};
            {
                const char* k0p = KH + (m0 + r) * RS + h * 32;
                uint32_t b0 = *reinterpret_cast<const uint32_t*>(k0p + 4 * j);
                uint32_t b1 = *reinterpret_cast<const uint32_t*>(k0p + 16 + 4 * j);
                mma16816(s0, q4[0], q4[1], q4[2], q4[3], b0, b1);
                const char* k1p = KH + (m0 + 8 + r) * RS + h * 32;
                b0 = *reinterpret_cast<const uint32_t*>(k1p + 4 * j);
                b1 = *reinterpret_cast<const uint32_t*>(k1p + 16 + 4 * j);
                mma16816(s1, q4[0], q4[1], q4[2], q4[3], b0, b1);
            }
            float e00 = __expf(s0[0]), e01 = __expf(s0[1]);
            float e10 = __expf(s1[0]), e11 = __expf(s1[1]);
            float f00 = __expf(s0[2]), f01 = __expf(s0[3]);
            float f10 = __expf(s1[2]), f11 = __expf(s1[3]);
            float sum0 = e00 + e01 + e10 + e11;
            float sum1 = f00 + f01 + f10 + f11;
            sum0 += __shfl_xor_sync(0xffffffffu, sum0, 1);
            sum0 += __shfl_xor_sync(0xffffffffu, sum0, 2);
            sum1 += __shfl_xor_sync(0xffffffffu, sum1, 1);
            sum1 += __shfl_xor_sync(0xffffffffu, sum1, 2);
            float iv0 = 1.f / sum0, iv1 = 1.f / sum1;
            uint32_t p0 = phi(e00, e01);
            uint32_t p1 = phi(f00, f01);
            uint32_t p2 = phi(e10, e11);
            uint32_t p3 = phi(f10, f11);
            float o0[4] = {0.f, 0.f, 0.f, 0.f}, o1[4] = {0.f, 0.f, 0.f, 0.f};
            {
                const char* v0p = vt + (h * 16 + r) * VTS;
                uint32_t b0 = *reinterpret_cast<const uint32_t*>(v0p + 4 * j);
                uint32_t b1 = *reinterpret_cast<const uint32_t*>(v0p + 16 + 4 * j);
                mma16816(o0, p0, p1, p2, p3, b0, b1);
                const char* v1p = vt + (h * 16 + 8 + r) * VTS;
                b0 = *reinterpret_cast<const uint32_t*>(v1p + 4 * j);
                b1 = *reinterpret_cast<const uint32_t*>(v1p + 16 + 4 * j);
                mma16816(o1, p0, p1, p2, p3, b0, b1);
            }
            oa[4*h+0] = phi(o0[0] * iv0, o0[1] * iv0);
            oa[4*h+1] = phi(o0[2] * iv1, o0[3] * iv1);
            oa[4*h+2] = phi(o1[0] * iv0, o1[1] * iv0);
            oa[4*h+3] = phi(o1[2] * iv1, o1[3] * iv1);
        }

        // -------- o @ Wo + bo + x ; LN1
        {
            float acc[8][4];
#pragma unroll
            for (int nt = 0; nt < 8; nt++) { acc[nt][0] = acc[nt][1] = acc[nt][2] = acc[nt][3] = 0.f; }
            gemm1<8>(oa, wl + 1536, acc, r, j);
#pragma unroll
            for (int nt = 0; nt < 8; nt++) {
                int c = nt * 8 + j * 2;
                float2 bb = __ldg(reinterpret_cast<const float2*>(bo + l * 64 + c));
                x[nt][0] += acc[nt][0] + bb.x; x[nt][1] += acc[nt][1] + bb.y;
                x[nt][2] += acc[nt][2] + bb.x; x[nt][3] += acc[nt][3] + bb.y;
            }
            ln_frag(x, ln1g + l * 64, ln1b + l * 64, j);
        }

        // -------- FF1 -> relu -> FF2 -> residual -> LN2
        {
            uint32_t fah[16];
            pack_hi_frags(x, fah);
            float t1[8][4];
#pragma unroll
            for (int nt = 0; nt < 8; nt++) { t1[nt][0] = t1[nt][1] = t1[nt][2] = t1[nt][3] = 0.f; }
            gemm1<8>(fah, wl + 2048, t1, r, j);
#pragma unroll
            for (int nt = 0; nt < 8; nt++) {
                int c = nt * 8 + j * 2;
                float2 bb = __ldg(reinterpret_cast<const float2*>(b1 + l * 64 + c));
                t1[nt][0] = fmaxf(t1[nt][0] + bb.x, 0.f); t1[nt][1] = fmaxf(t1[nt][1] + bb.y, 0.f);
                t1[nt][2] = fmaxf(t1[nt][2] + bb.x, 0.f); t1[nt][3] = fmaxf(t1[nt][3] + bb.y, 0.f);
            }
            uint32_t gah[16];
            pack_hi_frags(t1, gah);
            float acc[8][4];
#pragma unroll
            for (int nt = 0; nt < 8; nt++) { acc[nt][0] = acc[nt][1] = acc[nt][2] = acc[nt][3] = 0.f; }
            gemm1<8>(gah, wl + 2560, acc, r, j);
#pragma unroll
            for (int nt = 0; nt < 8; nt++) {
                int c = nt * 8 + j * 2;
                float2 bb = __ldg(reinterpret_cast<const float2*>(b2 + l * 64 + c));
                x[nt][0] += acc[nt][0] + bb.x; x[nt][1] += acc[nt][1] + bb.y;
                x[nt][2] += acc[nt][2] + bb.x; x[nt][3] += acc[nt][3] + bb.y;
            }
            ln_frag(x, ln2g + l * 64, ln2b + l * 64, j);
        }
    }

    // -------- final projection: out = x @ Wout + bout (3-term)
    {
        uint32_t fah[16], fal[16];
        pack_frags(x, fah, fal);
        float acc[12][4];
#pragma unroll
        for (int nt = 0; nt < 12; nt++) { acc[nt][0] = acc[nt][1] = acc[nt][2] = acc[nt][3] = 0.f; }
        gemm3<12>(fah, fal, g_wout, acc, r, j);
        float* o0 = out + (size_t)(blk * ROWS + m0 + r) * VOCAB;
        float* o1 = out + (size_t)(blk * ROWS + m0 + r + 8) * VOCAB;
#pragma unroll
        for (int nt = 0; nt < 12; nt++) {
            int c = nt * 8 + j * 2;
            float2 bb = __ldg(reinterpret_cast<const float2*>(bout + c));
            *reinterpret_cast<float2*>(o0 + c) = make_float2(acc[nt][0] + bb.x, acc[nt][1] + bb.y);
            *reinterpret_cast<float2*>(o1 + c) = make_float2(acc[nt][2] + bb.x, acc[nt][3] + bb.y);
        }
    }
}

extern "C" void kernel_launch(void* const* d_in, const int* in_sizes, int n_in,
                              void* d_out, int out_size) {
    const int*   data    = (const int*)d_in[0];
    const float* tok_emb = (const float*)d_in[1];
    const float* pos_emb = (const float*)d_in[2];
    const float* Wq      = (const float*)d_in[3];
    const float* Wk      = (const float*)d_in[4];
    const float* Wv      = (const float*)d_in[5];
    const float* Wo      = (const float*)d_in[6];
    const float* bo      = (const float*)d_in[7];
    const float* ln1g    = (const float*)d_in[8];
    const float* ln1b    = (const float*)d_in[9];
    const float* ln2g    = (const float*)d_in[10];
    const float* ln2b    = (const float*)d_in[11];
    const float* W1      = (const float*)d_in[12];
    const float* b1      = (const float*)d_in[13];
    const float* W2      = (const float*)d_in[14];
    const float* b2      = (const float*)d_in[15];
    const float* Wout    = (const float*)d_in[16];
    const float* bout    = (const float*)d_in[17];
    float* out = (float*)d_out;

    prep_kernel<<<(PREP_TOTAL + 255) / 256, 256>>>(Wq, Wk, Wv, Wo, W1, W2, Wout);
    cudaFuncSetAttribute(bert_mma_kernel,
                         cudaFuncAttributeMaxDynamicSharedMemorySize, SMEM_BYTES);
    bert_mma_kernel<<<BB / G, NT, SMEM_BYTES>>>(
        data, tok_emb, pos_emb, bo, ln1g, ln1b, ln2g, ln2b,
        b1, b2, bout, out);
}

// round 17
// speedup vs baseline: 1.2796x; 1.0639x over previous
#include <cuda_runtime.h>
#include <cuda_fp16.h>
#include <cstdint>

#define VOCAB 96
#define TT 16
#define EE 64
#define LL 4
#define BB 16384
#define G 4
#define ROWS 64
#define NT 128

#define RS 144            // fp16 row stride bytes for KH
#define VTS 40            // VT row stride bytes

#define O_KH   0
#define O_VT   9216
#define SMEM_BYTES (O_VT + 4 * 64 * VTS)   // 19456

// packed fp16 weights: 24 layer-slots x 512 units + final 768 units
// unit u = ((nt*2+kk)*8+r)*4+j holds k-steps 2kk,2kk+1 (lane-contiguous)
#define WPH_UNITS (24 * 512)
#define WFIN_UNITS 768
#define PREP_TOTAL (WPH_UNITS + WFIN_UNITS)

__device__ __align__(16) uint4 g_wph[PREP_TOTAL];

// ---------------- helpers ----------------
__device__ __forceinline__ uint32_t phh(float a, float b) {
    __half2 t = __floats2half2_rn(a, b);
    return *reinterpret_cast<uint32_t*>(&t);
}
__device__ __forceinline__ void mma16816(float d[4], uint32_t a0, uint32_t a1,
                                         uint32_t a2, uint32_t a3,
                                         uint32_t b0, uint32_t b1) {
    asm volatile(
        "mma.sync.aligned.m16n8k16.row.col.f32.f16.f16.f32 "
        "{%0,%1,%2,%3}, {%4,%5,%6,%7}, {%8,%9}, {%0,%1,%2,%3};"
        : "+f"(d[0]), "+f"(d[1]), "+f"(d[2]), "+f"(d[3])
        : "r"(a0), "r"(a1), "r"(a2), "r"(a3), "r"(b0), "r"(b1));
}
__device__ __forceinline__ void pack_hi_frags(const float act[8][4], uint32_t ah[16]) {
#pragma unroll
    for (int ks = 0; ks < 4; ks++) {
        const float* a0 = act[2 * ks];
        const float* a1 = act[2 * ks + 1];
        ah[4*ks+0] = phh(a0[0], a0[1]);
        ah[4*ks+1] = phh(a0[2], a0[3]);
        ah[4*ks+2] = phh(a1[0], a1[1]);
        ah[4*ks+3] = phh(a1[2], a1[3]);
    }
}
// 1-term fp16 GEMM, coalesced packed weights
template <int NTL>
__device__ __forceinline__ void gemm1(const uint32_t ah[16],
                                      const uint4* __restrict__ wu,
                                      float acc[NTL][4], int r, int j) {
    const uint4* base = wu + r * 4 + j;
#pragma unroll
    for (int nt = 0; nt < NTL; nt++) {
        uint4 bA = __ldg(base + nt * 64);
        uint4 bB = __ldg(base + nt * 64 + 32);
        mma16816(acc[nt], ah[0],  ah[1],  ah[2],  ah[3],  bA.x, bA.y);
        mma16816(acc[nt], ah[4],  ah[5],  ah[6],  ah[7],  bA.z, bA.w);
        mma16816(acc[nt], ah[8],  ah[9],  ah[10], ah[11], bB.x, bB.y);
        mma16816(acc[nt], ah[12], ah[13], ah[14], ah[15], bB.z, bB.w);
    }
}
__device__ __forceinline__ void fstore_hi(char* B, int m0, int r, int j,
                                          const float a[8][4]) {
#pragma unroll
    for (int nt = 0; nt < 8; nt++) {
        uint32_t co = (uint32_t)(nt * 16 + j * 4);
        *reinterpret_cast<uint32_t*>(B + (m0 + r) * RS + co) = phh(a[nt][0], a[nt][1]);
        *reinterpret_cast<uint32_t*>(B + (m0 + r + 8) * RS + co) = phh(a[nt][2], a[nt][3]);
    }
}
__device__ __forceinline__ void fstore_vt(char* vt, int r, int j, const float a[8][4]) {
#pragma unroll
    for (int nt = 0; nt < 8; nt++) {
        int c = nt * 8 + 2 * j;
        *reinterpret_cast<__half*>(vt + c * VTS + r * 2) = __float2half(a[nt][0]);
        *reinterpret_cast<__half*>(vt + (c + 1) * VTS + r * 2) = __float2half(a[nt][1]);
        *reinterpret_cast<__half*>(vt + c * VTS + (r + 8) * 2) = __float2half(a[nt][2]);
        *reinterpret_cast<__half*>(vt + (c + 1) * VTS + (r + 8) * 2) = __float2half(a[nt][3]);
    }
}
__device__ __forceinline__ void ln_frag(float x[8][4], const float* __restrict__ g,
                                        const float* __restrict__ b, int j) {
    float s0 = 0.f, q0 = 0.f, s1 = 0.f, q1 = 0.f;
#pragma unroll
    for (int nt = 0; nt < 8; nt++) {
        s0 += x[nt][0] + x[nt][1]; q0 += x[nt][0] * x[nt][0] + x[nt][1] * x[nt][1];
        s1 += x[nt][2] + x[nt][3]; q1 += x[nt][2] * x[nt][2] + x[nt][3] * x[nt][3];
    }
    s0 += __shfl_xor_sync(0xffffffffu, s0, 1); q0 += __shfl_xor_sync(0xffffffffu, q0, 1);
    s1 += __shfl_xor_sync(0xffffffffu, s1, 1); q1 += __shfl_xor_sync(0xffffffffu, q1, 1);
    s0 += __shfl_xor_sync(0xffffffffu, s0, 2); q0 += __shfl_xor_sync(0xffffffffu, q0, 2);
    s1 += __shfl_xor_sync(0xffffffffu, s1, 2); q1 += __shfl_xor_sync(0xffffffffu, q1, 2);
    float m0 = s0 * (1.f / 64.f), m1 = s1 * (1.f / 64.f);
    float r0 = rsqrtf(q0 * (1.f / 64.f) - m0 * m0 + 1e-5f);
    float r1 = rsqrtf(q1 * (1.f / 64.f) - m1 * m1 + 1e-5f);
#pragma unroll
    for (int nt = 0; nt < 8; nt++) {
        int c = nt * 8 + j * 2;
        float2 gg = __ldg(reinterpret_cast<const float2*>(g + c));
        float2 bb = __ldg(reinterpret_cast<const float2*>(b + c));
        x[nt][0] = (x[nt][0] - m0) * r0 * gg.x + bb.x;
        x[nt][1] = (x[nt][1] - m0) * r0 * gg.y + bb.y;
        x[nt][2] = (x[nt][2] - m1) * r1 * gg.x + bb.x;
        x[nt][3] = (x[nt][3] - m1) * r1 * gg.y + bb.y;
    }
}

// ---------------- prep kernel ----------------
__global__ void prep_kernel(const float* __restrict__ Wq, const float* __restrict__ Wk,
                            const float* __restrict__ Wv, const float* __restrict__ Wo,
                            const float* __restrict__ W1, const float* __restrict__ W2,
                            const float* __restrict__ Wout) {
    int gid = blockIdx.x * 256 + threadIdx.x;
    if (gid >= PREP_TOTAL) return;
    uint32_t res[4];
    if (gid < WPH_UNITS) {
        int sidx = gid >> 9;
        int u = gid & 511;
        int l = sidx / 6, slot = sidx % 6;
        int j = u & 3, r = (u >> 2) & 7, kk = (u >> 5) & 1, nt = u >> 6;
        int c = nt * 8 + r;
#pragma unroll
        for (int t = 0; t < 2; t++) {
            int k0 = (2 * kk + t) * 16 + j * 2;
            float v00, v01, v80, v81;
            if (slot < 3) {
                const float* W = (slot == 0) ? Wq : (slot == 1) ? Wk : Wv;
                const float* p = W + l * 4096 + (c >> 4) * 1024 + (c & 15);
                v00 = p[k0 * 16]; v01 = p[(k0 + 1) * 16];
                v80 = p[(k0 + 8) * 16]; v81 = p[(k0 + 9) * 16];
            } else {
                const float* W = (slot == 3) ? Wo : (slot == 4) ? W1 : W2;
                const float* p = W + l * 4096 + c;
                v00 = p[k0 * 64]; v01 = p[(k0 + 1) * 64];
                v80 = p[(k0 + 8) * 64]; v81 = p[(k0 + 9) * 64];
            }
            res[2 * t] = phh(v00, v01);
            res[2 * t + 1] = phh(v80, v81);
        }
    } else {
        int u = gid - WPH_UNITS;
        int j = u & 3, r = (u >> 2) & 7, kk = (u >> 5) & 1, nt = u >> 6;
        int c = nt * 8 + r;
#pragma unroll
        for (int t = 0; t < 2; t++) {
            int k0 = (2 * kk + t) * 16 + j * 2;
            const float* p = Wout + c;
            res[2 * t]     = phh(p[k0 * 96], p[(k0 + 1) * 96]);
            res[2 * t + 1] = phh(p[(k0 + 8) * 96], p[(k0 + 9) * 96]);
        }
    }
    g_wph[gid] = make_uint4(res[0], res[1], res[2], res[3]);
}

// ---------------- main kernel ----------------
__global__ void __launch_bounds__(NT, 4)
bert_mma_kernel(const int* __restrict__ data, const float* __restrict__ tok_emb,
                const float* __restrict__ pos_emb,
                const float* __restrict__ bo,
                const float* __restrict__ ln1g, const float* __restrict__ ln1b,
                const float* __restrict__ ln2g, const float* __restrict__ ln2b,
                const float* __restrict__ b1, const float* __restrict__ b2,
                const float* __restrict__ bout, float* __restrict__ out) {
    extern __shared__ char sm[];
    char* KH = sm + O_KH;

    const int tid = threadIdx.x;
    const int w = tid >> 5, lane = tid & 31;
    const int r = lane >> 2, j = lane & 3;
    const int m0 = w * 16;
    const int blk = blockIdx.x;
    char* vt = sm + O_VT + w * 64 * VTS;

    // -------- embedding (fragment layout)
    float x[8][4];
    {
        int b = blk * G + w;
        int tokA = data[b * TT + r], tokB = data[b * TT + r + 8];
#pragma unroll
        for (int nt = 0; nt < 8; nt++) {
            int c = nt * 8 + j * 2;
            float2 tA = __ldg(reinterpret_cast<const float2*>(tok_emb + tokA * EE + c));
            float2 tB = __ldg(reinterpret_cast<const float2*>(tok_emb + tokB * EE + c));
            float2 pA = __ldg(reinterpret_cast<const float2*>(pos_emb + r * EE + c));
            float2 pB = __ldg(reinterpret_cast<const float2*>(pos_emb + (r + 8) * EE + c));
            x[nt][0] = tA.x + pA.x; x[nt][1] = tA.y + pA.y;
            x[nt][2] = tB.x + pB.x; x[nt][3] = tB.y + pB.y;
        }
    }

    for (int l = 0; l < LL; l++) {
        const uint4* wl = g_wph + l * 3072;

        uint32_t pah[16];
        pack_hi_frags(x, pah);

        // Q -> registers (A-frags per head, pre-scaled by 0.25)
        uint32_t qa[16];
        {
            float acc[8][4];
#pragma unroll
            for (int nt = 0; nt < 8; nt++) { acc[nt][0] = acc[nt][1] = acc[nt][2] = acc[nt][3] = 0.f; }
            gemm1<8>(pah, wl + 0, acc, r, j);
#pragma unroll
            for (int h = 0; h < 4; h++) {
                qa[4*h+0] = phh(acc[2*h][0] * 0.25f, acc[2*h][1] * 0.25f);
                qa[4*h+1] = phh(acc[2*h][2] * 0.25f, acc[2*h][3] * 0.25f);
                qa[4*h+2] = phh(acc[2*h+1][0] * 0.25f, acc[2*h+1][1] * 0.25f);
                qa[4*h+3] = phh(acc[2*h+1][2] * 0.25f, acc[2*h+1][3] * 0.25f);
            }
        }
        // K -> smem rows (fp16)
        {
            float acc[8][4];
#pragma unroll
            for (int nt = 0; nt < 8; nt++) { acc[nt][0] = acc[nt][1] = acc[nt][2] = acc[nt][3] = 0.f; }
            gemm1<8>(pah, wl + 512, acc, r, j);
            fstore_hi(KH, m0, r, j, acc);
        }
        // V -> smem transposed (fp16)
        {
            float acc[8][4];
#pragma unroll
            for (int nt = 0; nt < 8; nt++) { acc[nt][0] = acc[nt][1] = acc[nt][2] = acc[nt][3] = 0.f; }
            gemm1<8>(pah, wl + 1024, acc, r, j);
            fstore_vt(vt, r, j, acc);
        }
        __syncwarp();

        // -------- attention: fragment-native, no max-subtraction
        uint32_t oa[16];
#pragma unroll
        for (int h = 0; h < 4; h++) {
            const uint32_t* q4 = qa + 4 * h;
            float s0[4] = {0.f, 0.f, 0.f, 0.f}, s1[4] = {0.f, 0.f, 0.f, 0.f};
            {
                const char* k0p = KH + (m0 + r) * RS + h * 32;
                uint32_t b0 = *reinterpret_cast<const uint32_t*>(k0p + 4 * j);
                uint32_t b1 = *reinterpret_cast<const uint32_t*>(k0p + 16 + 4 * j);
                mma16816(s0, q4[0], q4[1], q4[2], q4[3], b0, b1);
                const char* k1p = KH + (m0 + 8 + r) * RS + h * 32;
                b0 = *reinterpret_cast<const uint32_t*>(k1p + 4 * j);
                b1 = *reinterpret_cast<const uint32_t*>(k1p + 16 + 4 * j);
                mma16816(s1, q4[0], q4[1], q4[2], q4[3], b0, b1);
            }
            float e00 = __expf(s0[0]), e01 = __expf(s0[1]);
            float e10 = __expf(s1[0]), e11 = __expf(s1[1]);
            float f00 = __expf(s0[2]), f01 = __expf(s0[3]);
            float f10 = __expf(s1[2]), f11 = __expf(s1[3]);
            float sum0 = e00 + e01 + e10 + e11;
            float sum1 = f00 + f01 + f10 + f11;
            sum0 += __shfl_xor_sync(0xffffffffu, sum0, 1);
            sum0 += __shfl_xor_sync(0xffffffffu, sum0, 2);
            sum1 += __shfl_xor_sync(0xffffffffu, sum1, 1);
            sum1 += __shfl_xor_sync(0xffffffffu, sum1, 2);
            float iv0 = 1.f / sum0, iv1 = 1.f / sum1;
            uint32_t p0 = phh(e00, e01);
            uint32_t p1 = phh(f00, f01);
            uint32_t p2 = phh(e10, e11);
            uint32_t p3 = phh(f10, f11);
            float o0[4] = {0.f, 0.f, 0.f, 0.f}, o1[4] = {0.f, 0.f, 0.f, 0.f};
            {
                const char* v0p = vt + (h * 16 + r) * VTS;
                uint32_t b0 = *reinterpret_cast<const uint32_t*>(v0p + 4 * j);
                uint32_t b1 = *reinterpret_cast<const uint32_t*>(v0p + 16 + 4 * j);
                mma16816(o0, p0, p1, p2, p3, b0, b1);
                const char* v1p = vt + (h * 16 + 8 + r) * VTS;
                b0 = *reinterpret_cast<const uint32_t*>(v1p + 4 * j);
                b1 = *reinterpret_cast<const uint32_t*>(v1p + 16 + 4 * j);
                mma16816(o1, p0, p1, p2, p3, b0, b1);
            }
            oa[4*h+0] = phh(o0[0] * iv0, o0[1] * iv0);
            oa[4*h+1] = phh(o0[2] * iv1, o0[3] * iv1);
            oa[4*h+2] = phh(o1[0] * iv0, o1[1] * iv0);
            oa[4*h+3] = phh(o1[2] * iv1, o1[3] * iv1);
        }

        // -------- o @ Wo + bo + x ; LN1
        {
            float acc[8][4];
#pragma unroll
            for (int nt = 0; nt < 8; nt++) { acc[nt][0] = acc[nt][1] = acc[nt][2] = acc[nt][3] = 0.f; }
            gemm1<8>(oa, wl + 1536, acc, r, j);
#pragma unroll
            for (int nt = 0; nt < 8; nt++) {
                int c = nt * 8 + j * 2;
                float2 bb = __ldg(reinterpret_cast<const float2*>(bo + l * 64 + c));
                x[nt][0] += acc[nt][0] + bb.x; x[nt][1] += acc[nt][1] + bb.y;
                x[nt][2] += acc[nt][2] + bb.x; x[nt][3] += acc[nt][3] + bb.y;
            }
            ln_frag(x, ln1g + l * 64, ln1b + l * 64, j);
        }

        // -------- FF1 -> relu -> FF2 -> residual -> LN2
        {
            uint32_t fah[16];
            pack_hi_frags(x, fah);
            float t1[8][4];
#pragma unroll
            for (int nt = 0; nt < 8; nt++) { t1[nt][0] = t1[nt][1] = t1[nt][2] = t1[nt][3] = 0.f; }
            gemm1<8>(fah, wl + 2048, t1, r, j);
#pragma unroll
            for (int nt = 0; nt < 8; nt++) {
                int c = nt * 8 + j * 2;
                float2 bb = __ldg(reinterpret_cast<const float2*>(b1 + l * 64 + c));
                t1[nt][0] = fmaxf(t1[nt][0] + bb.x, 0.f); t1[nt][1] = fmaxf(t1[nt][1] + bb.y, 0.f);
                t1[nt][2] = fmaxf(t1[nt][2] + bb.x, 0.f); t1[nt][3] = fmaxf(t1[nt][3] + bb.y, 0.f);
            }
            uint32_t gah[16];
            pack_hi_frags(t1, gah);
            float acc[8][4];
#pragma unroll
            for (int nt = 0; nt < 8; nt++) { acc[nt][0] = acc[nt][1] = acc[nt][2] = acc[nt][3] = 0.f; }
            gemm1<8>(gah, wl + 2560, acc, r, j);
#pragma unroll
            for (int nt = 0; nt < 8; nt++) {
                int c = nt * 8 + j * 2;
                float2 bb = __ldg(reinterpret_cast<const float2*>(b2 + l * 64 + c));
                x[nt][0] += acc[nt][0] + bb.x; x[nt][1] += acc[nt][1] + bb.y;
                x[nt][2] += acc[nt][2] + bb.x; x[nt][3] += acc[nt][3] + bb.y;
            }
            ln_frag(x, ln2g + l * 64, ln2b + l * 64, j);
        }
    }

    // -------- final projection: out = x @ Wout + bout (1-term fp16)
    {
        uint32_t fah[16];
        pack_hi_frags(x, fah);
        float acc[12][4];
#pragma unroll
        for (int nt = 0; nt < 12; nt++) { acc[nt][0] = acc[nt][1] = acc[nt][2] = acc[nt][3] = 0.f; }
        gemm1<12>(fah, g_wph + WPH_UNITS, acc, r, j);
        float* o0 = out + (size_t)(blk * ROWS + m0 + r) * VOCAB;
        float* o1 = out + (size_t)(blk * ROWS + m0 + r + 8) * VOCAB;
#pragma unroll
        for (int nt = 0; nt < 12; nt++) {
            int c = nt * 8 + j * 2;
            float2 bb = __ldg(reinterpret_cast<const float2*>(bout + c));
            *reinterpret_cast<float2*>(o0 + c) = make_float2(acc[nt][0] + bb.x, acc[nt][1] + bb.y);
            *reinterpret_cast<float2*>(o1 + c) = make_float2(acc[nt][2] + bb.x, acc[nt][3] + bb.y);
        }
    }
}

extern "C" void kernel_launch(void* const* d_in, const int* in_sizes, int n_in,
                              void* d_out, int out_size) {
    const int*   data    = (const int*)d_in[0];
    const float* tok_emb = (const float*)d_in[1];
    const float* pos_emb = (const float*)d_in[2];
    const float* Wq      = (const float*)d_in[3];
    const float* Wk      = (const float*)d_in[4];
    const float* Wv      = (const float*)d_in[5];
    const float* Wo      = (const float*)d_in[6];
    const float* bo      = (const float*)d_in[7];
    const float* ln1g    = (const float*)d_in[8];
    const float* ln1b    = (const float*)d_in[9];
    const float* ln2g    = (const float*)d_in[10];
    const float* ln2b    = (const float*)d_in[11];
    const float* W1      = (const float*)d_in[12];
    const float* b1      = (const float*)d_in[13];
    const float* W2      = (const float*)d_in[14];
    const float* b2      = (const float*)d_in[15];
    const float* Wout    = (const float*)d_in[16];
    const float* bout    = (const float*)d_in[17];
    float* out = (float*)d_out;

    prep_kernel<<<(PREP_TOTAL + 255) / 256, 256>>>(Wq, Wk, Wv, Wo, W1, W2, Wout);
    cudaFuncSetAttribute(bert_mma_kernel,
                         cudaFuncAttributeMaxDynamicSharedMemorySize, SMEM_BYTES);
    bert_mma_kernel<<<BB / G, NT, SMEM_BYTES>>>(
        data, tok_emb, pos_emb, bo, ln1g, ln1b, ln2g, ln2b,
        b1, b2, bout, out);
}